// round 9
// baseline (speedup 1.0000x reference)
#include <cuda_runtime.h>
#include <math.h>

// Problem constants
#define Vv 32000
#define Ee 512
#define Hh 512
#define Ll 2
#define Bb 64
#define Tt 256
#define G4 2048   // 4*H
#define GRID 128  // persistent CTAs (<=148 SMs, 1 CTA/SM -> all resident)

typedef unsigned long long ull;

// ---------------- device scratch (no allocations allowed) ----------------
__device__ float g_WT_fc[Ee * Vv];        // [k][v]   transposed W_fc
__device__ float g_WT_ih[Ll][Ee * G4];    // [l][k][j]
__device__ float g_WT_hh[Ll][Hh * G4];    // [l][k][j]
__device__ float g_h[2][Ll][Hh * Bb];     // [ping][l][u*64+b]  (k-major over batch)
__device__ float g_c[Ll][Hh * Bb];        // [l][u*64+b]
__device__ float g_x[Ee * Bb];            // [k][b] current input embedding
__device__ ull   g_amax[Bb];              // packed (orderable float | ~idx) argmax
__device__ unsigned g_bar_count;
__device__ volatile unsigned g_bar_gen;

// ---------------- packed f32x2 FMA helpers --------------------------------
__device__ __forceinline__ void ffma2(ull& d, ull a, ull b) {
    asm("fma.rn.f32x2 %0, %1, %2, %0;" : "+l"(d) : "l"(a), "l"(b));
}
__device__ __forceinline__ ull pack2(float v) {
    ull r; asm("mov.b64 %0, {%1, %1};" : "=l"(r) : "f"(v)); return r;
}
__device__ __forceinline__ float2 unpack2(ull a) {
    float2 r; asm("mov.b64 {%0, %1}, %2;" : "=f"(r.x), "=f"(r.y) : "l"(a)); return r;
}

// argmax key: monotone-orderable float, ties -> lowest index wins
__device__ __forceinline__ ull amax_pack(float f, int idx) {
    unsigned b = __float_as_uint(f);
    unsigned key = (b & 0x80000000u) ? ~b : (b | 0x80000000u);
    return ((ull)key << 32) | (ull)(0xFFFFFFFFu - (unsigned)idx);
}

// ---------------- grid-wide barrier (all CTAs resident) --------------------
__device__ __forceinline__ void gsync() {
    __threadfence();          // each thread's global writes visible device-wide
    __syncthreads();
    if (threadIdx.x == 0) {
        unsigned gen = g_bar_gen;
        unsigned t = atomicAdd(&g_bar_count, 1u);
        if (t == GRID - 1) {
            g_bar_count = 0;
            __threadfence();
            g_bar_gen = gen + 1;
        } else {
            while (g_bar_gen == gen) { }
        }
    }
    __syncthreads();
}

// ---------------- transpose: src[R][C] -> dst[C][R] ------------------------
__global__ void ktranspose(const float* __restrict__ src, float* __restrict__ dst,
                           int R, int C) {
    __shared__ float tile[32][33];
    int c0 = blockIdx.x * 32, r0 = blockIdx.y * 32;
    int x = threadIdx.x, y0 = threadIdx.y;           // block (32, 8)
    #pragma unroll
    for (int dy = 0; dy < 32; dy += 8) {
        int r = r0 + y0 + dy, c = c0 + x;
        if (r < R && c < C) tile[y0 + dy][x] = src[r * C + c];
    }
    __syncthreads();
    #pragma unroll
    for (int dy = 0; dy < 32; dy += 8) {
        int c = c0 + y0 + dy, r = r0 + x;
        if (r < R && c < C) dst[c * R + r] = tile[x][y0 + dy];
    }
}

// ---------------- init: zero states / barrier / amax -----------------------
__global__ void kinit() {
    int i = blockIdx.x * blockDim.x + threadIdx.x;
    if (i < 2 * Ll * Hh * Bb) ((float*)g_h)[i] = 0.0f;
    if (i < Ll * Hh * Bb)     ((float*)g_c)[i] = 0.0f;
    if (i < Bb)               g_amax[i] = 0ull;
    if (i == 0) { g_bar_count = 0; g_bar_gen = 0; }
}

// ---------------- init: x0 = embedding[x[:,0]] -----------------------------
__global__ void kinit_x(const int* __restrict__ x, const float* __restrict__ emb) {
    int b = blockIdx.x;
    int tok = x[b * Tt];
    for (int k = threadIdx.x; k < Ee; k += blockDim.x)
        g_x[k * Bb + b] = emb[(size_t)tok * Ee + k];
}

// ---------------- LSTM layer phase (device function) -----------------------
// CTA owns 4 hidden units. warp w: gate q = w>>1, batch half bh = w&1.
// lane: u = lane&3 (unit), bg = lane>>2 (batch quad) -> 4 batch, 2 f32x2 accs.
__device__ __forceinline__ void lstm_layer(
    float* sh, float (*gbuf)[256],
    const float* __restrict__ inp,   // [512][64]  (cross-CTA: read via ldcg)
    const float* __restrict__ hin,   // [512][64]
    float* __restrict__ hout,        // [512][64]  (write via stcg)
    float* __restrict__ cst,         // cell, CTA-private slice
    const float* __restrict__ W1T, const float* __restrict__ W2T,
    const float* __restrict__ bih, const float* __restrict__ bhh,
    int cta, int tid)
{
    int w = tid >> 5, lane = tid & 31;
    int q = w >> 1, bh = w & 1;
    int u = lane & 3, bg = lane >> 2;
    int bbase = bh * 32 + bg * 4;
    int u0 = cta * 4;
    int j = q * 512 + u0 + u;
    ull acc0 = 0ull, acc1 = 0ull;

    // phase 1: input @ W_ih^T
    for (int i = tid; i < (Hh * Bb) / 4; i += 256)
        ((float4*)sh)[i] = __ldcg(((const float4*)inp) + i);
    __syncthreads();
    {
        const float* W = W1T + j;
        #pragma unroll 16
        for (int k = 0; k < Ee; k++) {
            ull wp = pack2(W[k * G4]);
            ulonglong2 hv = *(const ulonglong2*)(sh + k * Bb + bbase);
            ffma2(acc0, hv.x, wp);
            ffma2(acc1, hv.y, wp);
        }
    }
    __syncthreads();
    // phase 2: h @ W_hh^T
    for (int i = tid; i < (Hh * Bb) / 4; i += 256)
        ((float4*)sh)[i] = __ldcg(((const float4*)hin) + i);
    __syncthreads();
    {
        const float* W = W2T + j;
        #pragma unroll 16
        for (int k = 0; k < Hh; k++) {
            ull wp = pack2(W[k * G4]);
            ulonglong2 hv = *(const ulonglong2*)(sh + k * Bb + bbase);
            ffma2(acc0, hv.x, wp);
            ffma2(acc1, hv.y, wp);
        }
    }

    float bsum = bih[j] + bhh[j];
    float2 a0 = unpack2(acc0), a1 = unpack2(acc1);
    *(float4*)&gbuf[q][u * 64 + bbase] =
        make_float4(a0.x + bsum, a0.y + bsum, a1.x + bsum, a1.y + bsum);
    __syncthreads();

    // cell update: 4 units x 64 batch = 256 elems, one per thread
    {
        int e = tid;
        int uu = e >> 6, b = e & 63;
        float iv = gbuf[0][e], fv = gbuf[1][e], gv = gbuf[2][e], ov = gbuf[3][e];
        int gi = (u0 + uu) * Bb + b;
        float co = cst[gi];
        float ig = 1.0f / (1.0f + expf(-iv));
        float fg = 1.0f / (1.0f + expf(-fv));
        float og = 1.0f / (1.0f + expf(-ov));
        float cn = fg * co + ig * tanhf(gv);
        float hn = og * tanhf(cn);
        cst[gi] = cn;
        __stcg(&hout[gi], hn);
    }
    __syncthreads();
}

// ---------------- persistent main kernel -----------------------------------
__global__ void __launch_bounds__(256, 1)
kmain(const float* __restrict__ emb,
      const float* __restrict__ b_ih, const float* __restrict__ b_hh,
      const float* __restrict__ bfc, float* __restrict__ out)
{
    extern __shared__ float sh[];            // 512*64 floats = 128 KB
    __shared__ float gbuf[4][256];
    __shared__ float swv[8][64];
    __shared__ int   swi[8][64];
    __shared__ int   s_tok;

    int tid = threadIdx.x, w = tid >> 5, lane = tid & 31;
    int cta = blockIdx.x;
    const int HS = Hh * Bb;

    for (int t = 0; t < Tt; t++) {
        int pi = t & 1, po = pi ^ 1;

        // ---- phase A: layer 0 (input = g_x)
        lstm_layer(sh, gbuf, g_x, &g_h[pi][0][0], &g_h[po][0][0], &g_c[0][0],
                   g_WT_ih[0], g_WT_hh[0], b_ih, b_hh, cta, tid);
        gsync();

        // ---- phase B: layer 1 (input = fresh layer-0 h)
        lstm_layer(sh, gbuf, &g_h[po][0][0], &g_h[pi][1][0], &g_h[po][1][0], &g_c[1][0],
                   g_WT_ih[1], g_WT_hh[1], b_ih + G4, b_hh + G4, cta, tid);
        gsync();

        // ---- phase C: FC head on h1  (CTAs 0..124, 256 vocab cols each)
        if (cta < 125) {
            for (int i = tid; i < HS / 4; i += 256)
                ((float4*)sh)[i] = __ldcg(((const float4*)&g_h[po][1][0]) + i);
            __syncthreads();

            int v = cta * 256 + tid;
            ull acc[32];
            #pragma unroll
            for (int p = 0; p < 32; p++) acc[p] = 0ull;

            const float* Wp = g_WT_fc + v;
            #pragma unroll 2
            for (int k = 0; k < Hh; k++) {
                ull wp = pack2(Wp[(size_t)k * Vv]);
                const ulonglong2* hp = (const ulonglong2*)(sh + k * Bb);
                #pragma unroll
                for (int p = 0; p < 16; p++) {
                    ulonglong2 hv = hp[p];
                    ffma2(acc[2 * p],     hv.x, wp);
                    ffma2(acc[2 * p + 1], hv.y, wp);
                }
            }

            float bv = bfc[v];
            #pragma unroll
            for (int p = 0; p < 32; p++) {   // acc[p] -> batches 2p, 2p+1
                float2 t2 = unpack2(acc[p]);
                float v0 = t2.x + bv;
                float v1 = t2.y + bv;
                if (t == Tt - 1) {
                    out[(size_t)(2 * p) * Vv + v]     = v0;
                    out[(size_t)(2 * p + 1) * Vv + v] = v1;
                } else {
                    // warp argmax for b = 2p
                    float mv = v0; int mi = v;
                    #pragma unroll
                    for (int o = 16; o > 0; o >>= 1) {
                        float ovv = __shfl_down_sync(0xffffffffu, mv, o);
                        int   oii = __shfl_down_sync(0xffffffffu, mi, o);
                        if (ovv > mv || (ovv == mv && oii < mi)) { mv = ovv; mi = oii; }
                    }
                    if (lane == 0) { swv[w][2 * p] = mv; swi[w][2 * p] = mi; }
                    // warp argmax for b = 2p+1
                    mv = v1; mi = v;
                    #pragma unroll
                    for (int o = 16; o > 0; o >>= 1) {
                        float ovv = __shfl_down_sync(0xffffffffu, mv, o);
                        int   oii = __shfl_down_sync(0xffffffffu, mi, o);
                        if (ovv > mv || (ovv == mv && oii < mi)) { mv = ovv; mi = oii; }
                    }
                    if (lane == 0) { swv[w][2 * p + 1] = mv; swi[w][2 * p + 1] = mi; }
                }
            }
            if (t < Tt - 1) {
                __syncthreads();
                if (tid < 64) {
                    int b = tid;
                    float mv = swv[0][b]; int mi = swi[0][b];
                    #pragma unroll
                    for (int ww = 1; ww < 8; ww++) {
                        float ovv = swv[ww][b]; int oii = swi[ww][b];
                        if (ovv > mv || (ovv == mv && oii < mi)) { mv = ovv; mi = oii; }
                    }
                    atomicMax(&g_amax[b], amax_pack(mv, mi));
                }
            }
            __syncthreads();
        }
        gsync();

        // ---- phase D: pick token, gather next embedding into g_x
        if (t < Tt - 1 && cta < Bb) {
            if (tid == 0) {
                ull pv = __ldcg((const ull*)&g_amax[cta]);
                s_tok = (int)(0xFFFFFFFFu - (unsigned)(pv & 0xFFFFFFFFull));
                atomicExch(&g_amax[cta], 0ull);   // reset for next step
            }
            __syncthreads();
            int tok = s_tok;
            float2 e2 = *(const float2*)(emb + (size_t)tok * Ee + tid * 2);
            __stcg(&g_x[(tid * 2) * Bb + cta],     e2.x);
            __stcg(&g_x[(tid * 2 + 1) * Bb + cta], e2.y);
        }
        gsync();
    }
}

// ---------------- host driver ----------------------------------------------
extern "C" void kernel_launch(void* const* d_in, const int* in_sizes, int n_in,
                              void* d_out, int out_size) {
    const int*   x    = (const int*)d_in[0];
    const float* emb  = (const float*)d_in[1];
    const float* W_ih = (const float*)d_in[2];   // [2][2048][512]
    const float* W_hh = (const float*)d_in[3];   // [2][2048][512]
    const float* b_ih = (const float*)d_in[4];   // [2][2048]
    const float* b_hh = (const float*)d_in[5];
    const float* W_fc = (const float*)d_in[6];   // [32000][512]
    const float* b_fc = (const float*)d_in[7];
    float* out = (float*)d_out;

    float *pWfc, *pWih, *pWhh;
    cudaGetSymbolAddress((void**)&pWfc, g_WT_fc);
    cudaGetSymbolAddress((void**)&pWih, g_WT_ih);
    cudaGetSymbolAddress((void**)&pWhh, g_WT_hh);

    const int SMEM = Hh * Bb * (int)sizeof(float);   // 131072
    cudaFuncSetAttribute(kmain, cudaFuncAttributeMaxDynamicSharedMemorySize, SMEM);

    dim3 tb(32, 8);
    // transpose weights to k-major (5 nodes)
    ktranspose<<<dim3(Ee / 32, Vv / 32), tb>>>(W_fc, pWfc, Vv, Ee);
    for (int l = 0; l < Ll; l++) {
        ktranspose<<<dim3(Ee / 32, G4 / 32), tb>>>(W_ih + (size_t)l * G4 * Ee,
                                                   pWih + (size_t)l * Ee * G4, G4, Ee);
        ktranspose<<<dim3(Hh / 32, G4 / 32), tb>>>(W_hh + (size_t)l * G4 * Hh,
                                                   pWhh + (size_t)l * Hh * G4, G4, Hh);
    }
    kinit<<<512, 256>>>();
    kinit_x<<<Bb, 128>>>(x, emb);

    // one persistent kernel for all 256 timesteps
    kmain<<<GRID, 256, SMEM>>>(emb, b_ih, b_hh, b_fc, out);
}

// round 10
// speedup vs baseline: 1.1141x; 1.1141x over previous
#include <cuda_runtime.h>
#include <math.h>

// Problem constants
#define Vv 32000
#define Ee 512
#define Hh 512
#define Ll 2
#define Bb 64
#define Tt 256
#define G4 2048   // 4*H
#define GRID 128  // persistent CTAs, 1/SM (128KB smem) -> all co-resident

typedef unsigned long long ull;

// ---------------- device scratch (no allocations allowed) ----------------
__device__ float g_WT_fc[Ee * Vv];        // [k][v]   transposed W_fc (built in-kernel)
__device__ float g_h[2][Ll][Hh * Bb];     // [ping][l][u*64+b]  (k-major over batch)
__device__ float g_c[Ll][Hh * Bb];        // [l][u*64+b]
__device__ float g_x[Ee * Bb];            // [k][b] current input embedding
__device__ ull   g_amax[Bb];              // packed (orderable float | ~idx) argmax
__device__ unsigned g_bar_count;
__device__ volatile unsigned g_bar_gen;

// ---------------- packed f32x2 FMA helpers --------------------------------
__device__ __forceinline__ void ffma2(ull& d, ull a, ull b) {
    asm("fma.rn.f32x2 %0, %1, %2, %0;" : "+l"(d) : "l"(a), "l"(b));
}
__device__ __forceinline__ ull pack2(float v) {
    ull r; asm("mov.b64 %0, {%1, %1};" : "=l"(r) : "f"(v)); return r;
}
__device__ __forceinline__ float2 unpack2(ull a) {
    float2 r; asm("mov.b64 {%0, %1}, %2;" : "=f"(r.x), "=f"(r.y) : "l"(a)); return r;
}

// argmax key: monotone-orderable float, ties -> lowest index wins
__device__ __forceinline__ ull amax_pack(float f, int idx) {
    unsigned b = __float_as_uint(f);
    unsigned key = (b & 0x80000000u) ? ~b : (b | 0x80000000u);
    return ((ull)key << 32) | (ull)(0xFFFFFFFFu - (unsigned)idx);
}

// ---------------- grid-wide barrier (all CTAs resident) --------------------
__device__ __forceinline__ void gsync() {
    __threadfence();
    __syncthreads();
    if (threadIdx.x == 0) {
        unsigned gen = g_bar_gen;
        unsigned t = atomicAdd(&g_bar_count, 1u);
        if (t == GRID - 1) {
            g_bar_count = 0;
            __threadfence();
            g_bar_gen = gen + 1;
        } else {
            while (g_bar_gen == gen) { }
        }
    }
    __syncthreads();
}

// ---------------- 512-k dot with 8-deep double-buffered weight prefetch ----
// Wr: lane's weight row (original row-major layout, 128 float4 = 512 k)
// shk0: sh + bbase; activations sh[k*64 + b], stride 64 floats per k
__device__ __forceinline__ void gemm512(ull& acc0, ull& acc1,
                                        const float4* __restrict__ Wr,
                                        const float* __restrict__ shk0) {
    float4 buf[8], nbuf[8];
    #pragma unroll
    for (int p = 0; p < 8; p++) buf[p] = Wr[p];
    #pragma unroll 1
    for (int c = 0; c < 16; c++) {
        const float4* nx = Wr + ((c < 15) ? (c + 1) * 8 : 0);
        #pragma unroll
        for (int p = 0; p < 8; p++) nbuf[p] = nx[p];
        const float* shk = shk0 + (c * 32) * Bb;
        #pragma unroll
        for (int p = 0; p < 8; p++) {
            float wv0 = buf[p].x, wv1 = buf[p].y, wv2 = buf[p].z, wv3 = buf[p].w;
            {
                ull wp = pack2(wv0);
                ulonglong2 hv = *(const ulonglong2*)(shk + (p * 4 + 0) * Bb);
                ffma2(acc0, hv.x, wp); ffma2(acc1, hv.y, wp);
            }
            {
                ull wp = pack2(wv1);
                ulonglong2 hv = *(const ulonglong2*)(shk + (p * 4 + 1) * Bb);
                ffma2(acc0, hv.x, wp); ffma2(acc1, hv.y, wp);
            }
            {
                ull wp = pack2(wv2);
                ulonglong2 hv = *(const ulonglong2*)(shk + (p * 4 + 2) * Bb);
                ffma2(acc0, hv.x, wp); ffma2(acc1, hv.y, wp);
            }
            {
                ull wp = pack2(wv3);
                ulonglong2 hv = *(const ulonglong2*)(shk + (p * 4 + 3) * Bb);
                ffma2(acc0, hv.x, wp); ffma2(acc1, hv.y, wp);
            }
        }
        #pragma unroll
        for (int p = 0; p < 8; p++) buf[p] = nbuf[p];
    }
}

// ---------------- LSTM layer phase (device function) -----------------------
// CTA owns 4 hidden units. warp w: gate q = w>>1, batch half bh = w&1.
// lane: u = lane&3 (unit), bg = lane>>2 -> lane covers (1 j, 4 batches).
// Weights read directly from ORIGINAL [4H][E/H] row-major layout.
__device__ __forceinline__ void lstm_layer(
    float* sh, float (*gbuf)[256],
    const float* __restrict__ inp,   // [512][64]  cross-CTA: ldcg
    const float* __restrict__ hin,   // [512][64]
    float* __restrict__ hout,        // [512][64]  stcg
    float* __restrict__ cst,         // cell, CTA-private slice
    const float* __restrict__ W1,    // W_ih[l]  [2048][512]
    const float* __restrict__ W2,    // W_hh[l]  [2048][512]
    const float* __restrict__ bih, const float* __restrict__ bhh,
    int cta, int tid)
{
    int w = tid >> 5, lane = tid & 31;
    int q = w >> 1, bh = w & 1;
    int u = lane & 3, bg = lane >> 2;
    int bbase = bh * 32 + bg * 4;
    int u0 = cta * 4;
    int j = q * 512 + u0 + u;
    ull acc0 = 0ull, acc1 = 0ull;

    // phase 1: input @ W_ih^T
    for (int i = tid; i < (Hh * Bb) / 4; i += 256)
        ((float4*)sh)[i] = __ldcg(((const float4*)inp) + i);
    __syncthreads();
    gemm512(acc0, acc1, (const float4*)(W1 + (size_t)j * Ee), sh + bbase);
    __syncthreads();

    // phase 2: h @ W_hh^T
    for (int i = tid; i < (Hh * Bb) / 4; i += 256)
        ((float4*)sh)[i] = __ldcg(((const float4*)hin) + i);
    __syncthreads();
    gemm512(acc0, acc1, (const float4*)(W2 + (size_t)j * Hh), sh + bbase);

    float bsum = bih[j] + bhh[j];
    float2 a0 = unpack2(acc0), a1 = unpack2(acc1);
    *(float4*)&gbuf[q][u * 64 + bbase] =
        make_float4(a0.x + bsum, a0.y + bsum, a1.x + bsum, a1.y + bsum);
    __syncthreads();

    // cell update: 4 units x 64 batch = 256 elems, one per thread
    {
        int e = tid;
        int uu = e >> 6, b = e & 63;
        float iv = gbuf[0][e], fv = gbuf[1][e], gv = gbuf[2][e], ov = gbuf[3][e];
        int gi = (u0 + uu) * Bb + b;
        float co = cst[gi];
        float ig = 1.0f / (1.0f + expf(-iv));
        float fg = 1.0f / (1.0f + expf(-fv));
        float og = 1.0f / (1.0f + expf(-ov));
        float cn = fg * co + ig * tanhf(gv);
        float hn = og * tanhf(cn);
        cst[gi] = cn;
        __stcg(&hout[gi], hn);
    }
    __syncthreads();
}

// ---------------- single persistent kernel ---------------------------------
__global__ void __launch_bounds__(256, 1)
kmain(const int* __restrict__ x, const float* __restrict__ emb,
      const float* __restrict__ W_ih, const float* __restrict__ W_hh,
      const float* __restrict__ b_ih, const float* __restrict__ b_hh,
      const float* __restrict__ W_fc, const float* __restrict__ bfc,
      float* __restrict__ out)
{
    extern __shared__ float sh[];            // 512*64 floats = 128 KB
    __shared__ float gbuf[4][256];
    __shared__ float swv[8][64];
    __shared__ int   swi[8][64];
    __shared__ int   s_tok;

    int tid = threadIdx.x, w = tid >> 5, lane = tid & 31;
    int cta = blockIdx.x;
    const int HS = Hh * Bb;

    // ================= pre-loop init (every replay) =================
    {   // zero h, c, amax
        int gt = cta * 256 + tid;            // 0..32767
        float* hp = &g_h[0][0][0];
        #pragma unroll
        for (int r = 0; r < 4; r++) hp[r * 32768 + gt] = 0.0f;
        float* cp = &g_c[0][0];
        #pragma unroll
        for (int r = 0; r < 2; r++) cp[r * 32768 + gt] = 0.0f;
        if (gt < Bb) g_amax[gt] = 0ull;
    }
    if (cta < Bb) {                          // x0 = embedding[x[:,0]]
        int tok = x[cta * Tt];
        float2 e2 = ((const float2*)(emb + (size_t)tok * Ee))[tid];
        g_x[(2 * tid) * Bb + cta]     = e2.x;
        g_x[(2 * tid + 1) * Bb + cta] = e2.y;
    }
    {   // transpose W_fc slice: each CTA owns 250 vocab rows
        int v = cta * 250 + tid;
        if (tid < 250) {
            const float4* src = (const float4*)(W_fc + (size_t)v * Ee);
            #pragma unroll 4
            for (int kq = 0; kq < 128; kq++) {
                float4 r = src[kq];
                size_t k = (size_t)kq * 4;
                g_WT_fc[k * Vv + v]       = r.x;
                g_WT_fc[(k + 1) * Vv + v] = r.y;
                g_WT_fc[(k + 2) * Vv + v] = r.z;
                g_WT_fc[(k + 3) * Vv + v] = r.w;
            }
        }
    }
    gsync();

    // ================= timestep loop =================
    for (int t = 0; t < Tt; t++) {
        int pi = t & 1, po = pi ^ 1;

        // ---- phase A: layer 0
        lstm_layer(sh, gbuf, g_x, &g_h[pi][0][0], &g_h[po][0][0], &g_c[0][0],
                   W_ih, W_hh, b_ih, b_hh, cta, tid);
        gsync();

        // ---- phase B: layer 1
        lstm_layer(sh, gbuf, &g_h[po][0][0], &g_h[pi][1][0], &g_h[po][1][0], &g_c[1][0],
                   W_ih + (size_t)G4 * Ee, W_hh + (size_t)G4 * Hh,
                   b_ih + G4, b_hh + G4, cta, tid);
        gsync();

        // ---- phase C: FC head (CTAs 0..124, 256 vocab cols each)
        if (cta < 125) {
            for (int i = tid; i < HS / 4; i += 256)
                ((float4*)sh)[i] = __ldcg(((const float4*)&g_h[po][1][0]) + i);
            __syncthreads();

            int v = cta * 256 + tid;
            ull acc[32];
            #pragma unroll
            for (int p = 0; p < 32; p++) acc[p] = 0ull;

            const float* Wp = g_WT_fc + v;
            float wb[8], wn[8];
            #pragma unroll
            for (int p = 0; p < 8; p++) wb[p] = Wp[(size_t)p * Vv];
            #pragma unroll 1
            for (int c = 0; c < 64; c++) {
                const float* nx = Wp + (size_t)((c < 63) ? (c + 1) * 8 : 0) * Vv;
                #pragma unroll
                for (int p = 0; p < 8; p++) wn[p] = nx[(size_t)p * Vv];
                const ulonglong2* hp0 = (const ulonglong2*)(sh + (c * 8) * Bb);
                #pragma unroll
                for (int p = 0; p < 8; p++) {
                    ull wp = pack2(wb[p]);
                    const ulonglong2* hp = hp0 + p * 16;
                    #pragma unroll
                    for (int m = 0; m < 16; m++) {
                        ulonglong2 hv = hp[m];
                        ffma2(acc[2 * m],     hv.x, wp);
                        ffma2(acc[2 * m + 1], hv.y, wp);
                    }
                }
                #pragma unroll
                for (int p = 0; p < 8; p++) wb[p] = wn[p];
            }

            float bv = bfc[v];
            #pragma unroll
            for (int p = 0; p < 32; p++) {   // acc[p] -> batches 2p, 2p+1
                float2 t2 = unpack2(acc[p]);
                float v0 = t2.x + bv;
                float v1 = t2.y + bv;
                if (t == Tt - 1) {
                    out[(size_t)(2 * p) * Vv + v]     = v0;
                    out[(size_t)(2 * p + 1) * Vv + v] = v1;
                } else {
                    float mv = v0; int mi = v;
                    #pragma unroll
                    for (int o = 16; o > 0; o >>= 1) {
                        float ovv = __shfl_down_sync(0xffffffffu, mv, o);
                        int   oii = __shfl_down_sync(0xffffffffu, mi, o);
                        if (ovv > mv || (ovv == mv && oii < mi)) { mv = ovv; mi = oii; }
                    }
                    if (lane == 0) { swv[w][2 * p] = mv; swi[w][2 * p] = mi; }
                    mv = v1; mi = v;
                    #pragma unroll
                    for (int o = 16; o > 0; o >>= 1) {
                        float ovv = __shfl_down_sync(0xffffffffu, mv, o);
                        int   oii = __shfl_down_sync(0xffffffffu, mi, o);
                        if (ovv > mv || (ovv == mv && oii < mi)) { mv = ovv; mi = oii; }
                    }
                    if (lane == 0) { swv[w][2 * p + 1] = mv; swi[w][2 * p + 1] = mi; }
                }
            }
            if (t < Tt - 1) {
                __syncthreads();
                if (tid < 64) {
                    int b = tid;
                    float mv = swv[0][b]; int mi = swi[0][b];
                    #pragma unroll
                    for (int ww = 1; ww < 8; ww++) {
                        float ovv = swv[ww][b]; int oii = swi[ww][b];
                        if (ovv > mv || (ovv == mv && oii < mi)) { mv = ovv; mi = oii; }
                    }
                    atomicMax(&g_amax[b], amax_pack(mv, mi));
                }
            }
            __syncthreads();
        }
        gsync();

        // ---- phase D: pick token, gather next embedding into g_x
        if (t < Tt - 1 && cta < Bb) {
            if (tid == 0) {
                ull pv = __ldcg((const ull*)&g_amax[cta]);
                s_tok = (int)(0xFFFFFFFFu - (unsigned)(pv & 0xFFFFFFFFull));
                atomicExch(&g_amax[cta], 0ull);   // reset for next step
            }
            __syncthreads();
            int tok = s_tok;
            float2 e2 = *(const float2*)(emb + (size_t)tok * Ee + tid * 2);
            __stcg(&g_x[(tid * 2) * Bb + cta],     e2.x);
            __stcg(&g_x[(tid * 2 + 1) * Bb + cta], e2.y);
        }
        gsync();
    }
}

// ---------------- host driver ----------------------------------------------
extern "C" void kernel_launch(void* const* d_in, const int* in_sizes, int n_in,
                              void* d_out, int out_size) {
    const int*   x    = (const int*)d_in[0];
    const float* emb  = (const float*)d_in[1];
    const float* W_ih = (const float*)d_in[2];   // [2][2048][512]
    const float* W_hh = (const float*)d_in[3];   // [2][2048][512]
    const float* b_ih = (const float*)d_in[4];   // [2][2048]
    const float* b_hh = (const float*)d_in[5];
    const float* W_fc = (const float*)d_in[6];   // [32000][512]
    const float* b_fc = (const float*)d_in[7];
    float* out = (float*)d_out;

    const int SMEM = Hh * Bb * (int)sizeof(float);   // 131072
    cudaFuncSetAttribute(kmain, cudaFuncAttributeMaxDynamicSharedMemorySize, SMEM);

    // ONE launch: prep + all 256 timesteps inside (graph = 1 node)
    kmain<<<GRID, 256, SMEM>>>(x, emb, W_ih, W_hh, b_ih, b_hh, W_fc, b_fc, out);
}

// round 11
// speedup vs baseline: 1.7857x; 1.6028x over previous
#include <cuda_runtime.h>
#include <math.h>

// Problem constants
#define Vv 32000
#define Ee 512
#define Hh 512
#define G4 2048   // 4*H
#define Bb 64
#define Tt 256
#define GRID 128  // persistent CTAs, 1/SM (128KB smem) -> all co-resident

typedef unsigned long long ull;

// ---------------- device scratch (no allocations allowed) ----------------
__device__ float g_WT_fc[(size_t)Ee * Vv];   // [k][v] transposed W_fc
__device__ float g_h[2][2][Hh * Bb];         // [ping][layer][unit*64+b]
__device__ float g_x[Ee * Bb];               // [k][b] current input embedding
__device__ ull   g_amax[Bb];                 // packed (orderable float | ~idx)
__device__ unsigned g_bar_count;
__device__ volatile unsigned g_bar_gen;

// ---------------- packed f32x2 FMA helpers --------------------------------
__device__ __forceinline__ void ffma2(ull& d, ull a, ull b) {
    asm("fma.rn.f32x2 %0, %1, %2, %0;" : "+l"(d) : "l"(a), "l"(b));
}
__device__ __forceinline__ ull pack2(float v) {
    ull r; asm("mov.b64 %0, {%1, %1};" : "=l"(r) : "f"(v)); return r;
}
__device__ __forceinline__ float2 unpack2(ull a) {
    float2 r; asm("mov.b64 {%0, %1}, %2;" : "=f"(r.x), "=f"(r.y) : "l"(a)); return r;
}

// argmax key: monotone-orderable float, ties -> lowest index wins
__device__ __forceinline__ ull amax_pack(float f, int idx) {
    unsigned b = __float_as_uint(f);
    unsigned key = (b & 0x80000000u) ? ~b : (b | 0x80000000u);
    return ((ull)key << 32) | (ull)(0xFFFFFFFFu - (unsigned)idx);
}

// ---------------- grid-wide barrier (all CTAs resident) --------------------
// Relative-phase: works from any starting g_bar_gen value (no reset needed).
__device__ __forceinline__ void gsync() {
    __threadfence();
    __syncthreads();
    if (threadIdx.x == 0) {
        unsigned gen = g_bar_gen;
        unsigned t = atomicAdd(&g_bar_count, 1u);
        if (t == GRID - 1) {
            g_bar_count = 0;
            __threadfence();
            g_bar_gen = gen + 1;
        } else {
            while (g_bar_gen == gen) { }
        }
    }
    __syncthreads();
}

// ---------------- gates matmul: 512-k dot, weights in smem [k][4] ----------
// acc01 packs gates (i,f); acc23 packs (g,o).  actb: element b of k=0,
// stride 64 floats per k, read via coalesced LDG (16-deep ping-pong).
__device__ __forceinline__ void mm512(ull& acc01, ull& acc23,
                                      unsigned wofs,
                                      const float* __restrict__ actb) {
    extern __shared__ float wsm[];
    const ulonglong2* wq = (const ulonglong2*)(wsm + wofs);  // wq[k] = (w_if, w_go)
    float a0[16], a1[16];
    #pragma unroll
    for (int i = 0; i < 16; i++) a0[i] = __ldcg(actb + i * Bb);
    int k = 0;
    #pragma unroll 1
    for (int c = 0; c < 16; c++) {           // 16 iterations x 32 k
        #pragma unroll
        for (int i = 0; i < 16; i++) a1[i] = __ldcg(actb + (k + 16 + i) * Bb);
        #pragma unroll
        for (int i = 0; i < 16; i++) {
            ulonglong2 wv = wq[k + i];
            ull ap = pack2(a0[i]);
            ffma2(acc01, wv.x, ap);
            ffma2(acc23, wv.y, ap);
        }
        int ka = (c < 15) ? (k + 32) : 0;
        #pragma unroll
        for (int i = 0; i < 16; i++) a0[i] = __ldcg(actb + (ka + i) * Bb);
        #pragma unroll
        for (int i = 0; i < 16; i++) {
            ulonglong2 wv = wq[k + 16 + i];
            ull ap = pack2(a1[i]);
            ffma2(acc01, wv.x, ap);
            ffma2(acc23, wv.y, ap);
        }
        k += 32;
    }
}

// ---------------- LSTM layer: thread owns (1 unit, 1 batch, all 4 gates) ---
__device__ __forceinline__ void lstm_layer(
    int lrow,                            // smem row group base: layer*8
    const float* __restrict__ inp,       // [512][64]
    const float* __restrict__ hin,       // [512][64]
    float* __restrict__ hout,            // [512][64]
    float& creg,                         // cell state (register-resident)
    const float* __restrict__ bih, const float* __restrict__ bhh,
    int cta, int tid)
{
    int u = tid >> 6, b = tid & 63;
    ull acc01 = 0ull, acc23 = 0ull;
    mm512(acc01, acc23, (unsigned)(lrow + u)     * 2048, inp + b);   // W_ih
    mm512(acc01, acc23, (unsigned)(lrow + 4 + u) * 2048, hin + b);   // W_hh
    int j0 = cta * 4 + u;
    float2 a01 = unpack2(acc01), a23 = unpack2(acc23);
    float iv = a01.x + bih[j0]        + bhh[j0];
    float fv = a01.y + bih[512 + j0]  + bhh[512 + j0];
    float gv = a23.x + bih[1024 + j0] + bhh[1024 + j0];
    float ov = a23.y + bih[1536 + j0] + bhh[1536 + j0];
    float ig = 1.0f / (1.0f + expf(-iv));
    float fg = 1.0f / (1.0f + expf(-fv));
    float og = 1.0f / (1.0f + expf(-ov));
    float cn = fg * creg + ig * tanhf(gv);
    float hn = og * tanhf(cn);
    creg = cn;
    __stcg(&hout[j0 * Bb + b], hn);
}

// ---------------- single persistent kernel ---------------------------------
__global__ void __launch_bounds__(256, 1)
kmain(const int* __restrict__ x, const float* __restrict__ emb,
      const float* __restrict__ W_ih, const float* __restrict__ W_hh,
      const float* __restrict__ b_ih, const float* __restrict__ b_hh,
      const float* __restrict__ W_fc, const float* __restrict__ bfc,
      float* __restrict__ out)
{
    extern __shared__ float wsm[];       // 32768 floats = 128 KB gate weights
    __shared__ int s_tok;

    int tid = threadIdx.x;
    int cta = blockIdx.x;

    // ================= per-replay init =================
    // zero h ping 0 (both layers): 32768 float2 across 128x256 threads
    ((float2*)&g_h[0][0][0])[cta * 256 + tid] = make_float2(0.0f, 0.0f);

    // x0 = embedding[x[:,0]]  (CTAs 0..63)
    if (cta < Bb) {
        int tok = x[cta * Tt];
        float2 e2 = ((const float2*)(emb + (size_t)tok * Ee))[tid];
        g_x[(2 * tid) * Bb + cta]     = e2.x;
        g_x[(2 * tid + 1) * Bb + cta] = e2.y;
    }

    // gate weights -> smem, packed [row][k][q]; row = l*8 + m*4 + u
    #pragma unroll 1
    for (int r = 0; r < 16; r++) {
        int l = r >> 3, m = (r >> 2) & 1, u = r & 3;
        const float* base = (m ? W_hh : W_ih) + (size_t)l * G4 * 512;
        #pragma unroll
        for (int q = 0; q < 4; q++) {
            const float* src = base + (size_t)(q * 512 + cta * 4 + u) * 512;
            float2 v = *(const float2*)(src + tid * 2);
            wsm[r * 2048 + (tid * 2) * 4 + q]     = v.x;
            wsm[r * 2048 + (tid * 2 + 1) * 4 + q] = v.y;
        }
    }

    // transpose W_fc -> g_WT_fc [k][v]: each CTA owns 250 vocab rows
    if (tid < 250) {
        int v = cta * 250 + tid;
        const float4* src = (const float4*)(W_fc + (size_t)v * Ee);
        #pragma unroll 4
        for (int kq = 0; kq < 128; kq++) {
            float4 r = src[kq];
            size_t k = (size_t)kq * 4;
            g_WT_fc[k * Vv + v]       = r.x;
            g_WT_fc[(k + 1) * Vv + v] = r.y;
            g_WT_fc[(k + 2) * Vv + v] = r.z;
            g_WT_fc[(k + 3) * Vv + v] = r.w;
        }
    }

    float creg0 = 0.0f, creg1 = 0.0f;    // register-resident cell states
    gsync();

    // ================= timestep loop =================
    for (int t = 0; t < Tt; t++) {
        int pi = t & 1, po = pi ^ 1;

        // ---- layer 0
        lstm_layer(0, g_x, &g_h[pi][0][0], &g_h[po][0][0], creg0,
                   b_ih, b_hh, cta, tid);
        gsync();

        // ---- layer 1
        lstm_layer(8, &g_h[po][0][0], &g_h[pi][1][0], &g_h[po][1][0], creg1,
                   b_ih + G4, b_hh + G4, cta, tid);
        gsync();

        // ---- FC head: thread tile = 8 vocab x 8 batch (CTAs 0..124)
        if (cta < 125) {
            int bq = tid >> 5, vg = tid & 31;
            int v0 = cta * 256 + vg * 8;
            const float* hb = &g_h[po][1][0] + bq * 8;

            ull acc[8][4];
            #pragma unroll
            for (int v = 0; v < 8; v++) {
                acc[v][0] = 0; acc[v][1] = 0; acc[v][2] = 0; acc[v][3] = 0;
            }

            float4 wA[2][2], wB[2][2];
            ulonglong2 aA[2][2], aB[2][2];

#define FCLOAD(W, A, kk) { \
    const float4* wr0 = (const float4*)(g_WT_fc + (size_t)(kk) * Vv + v0);       \
    const float4* wr1 = (const float4*)(g_WT_fc + (size_t)((kk) + 1) * Vv + v0); \
    W[0][0] = wr0[0]; W[0][1] = wr0[1];                                          \
    W[1][0] = wr1[0]; W[1][1] = wr1[1];                                          \
    const ulonglong2* ar0 = (const ulonglong2*)(hb + (kk) * Bb);                 \
    const ulonglong2* ar1 = (const ulonglong2*)(hb + ((kk) + 1) * Bb);           \
    A[0][0] = __ldcg(ar0); A[0][1] = __ldcg(ar0 + 1);                            \
    A[1][0] = __ldcg(ar1); A[1][1] = __ldcg(ar1 + 1); }

#define FCCOMP(W, A) {                                                           \
    _Pragma("unroll")                                                            \
    for (int kk = 0; kk < 2; kk++) {                                             \
        ull ap0 = A[kk][0].x, ap1 = A[kk][0].y;                                  \
        ull ap2 = A[kk][1].x, ap3 = A[kk][1].y;                                  \
        const float* wf = (const float*)&W[kk][0];                               \
        _Pragma("unroll")                                                        \
        for (int v = 0; v < 8; v++) {                                            \
            ull wp = pack2(wf[v]);                                               \
            ffma2(acc[v][0], ap0, wp);                                           \
            ffma2(acc[v][1], ap1, wp);                                           \
            ffma2(acc[v][2], ap2, wp);                                           \
            ffma2(acc[v][3], ap3, wp);                                           \
        } } }

            FCLOAD(wA, aA, 0);
            #pragma unroll 1
            for (int k = 0; k < 512; k += 4) {
                int k2 = (k + 2 < 512) ? k + 2 : 0;
                FCLOAD(wB, aB, k2);
                FCCOMP(wA, aA);
                int k4 = (k + 4 < 512) ? k + 4 : 0;
                FCLOAD(wA, aA, k4);
                FCCOMP(wB, aB);
            }
#undef FCLOAD
#undef FCCOMP

            float bias[8];
            {
                float4 b0 = *(const float4*)(bfc + v0);
                float4 b1 = *(const float4*)(bfc + v0 + 4);
                bias[0] = b0.x; bias[1] = b0.y; bias[2] = b0.z; bias[3] = b0.w;
                bias[4] = b1.x; bias[5] = b1.y; bias[6] = b1.z; bias[7] = b1.w;
            }
            #pragma unroll
            for (int bb = 0; bb < 8; bb++) {
                int b = bq * 8 + bb;
                float vals[8];
                #pragma unroll
                for (int v = 0; v < 8; v++) {
                    float2 t2 = unpack2(acc[v][bb >> 1]);
                    vals[v] = ((bb & 1) ? t2.y : t2.x) + bias[v];
                }
                if (t == Tt - 1) {
                    *(float4*)(out + (size_t)b * Vv + v0) =
                        make_float4(vals[0], vals[1], vals[2], vals[3]);
                    *(float4*)(out + (size_t)b * Vv + v0 + 4) =
                        make_float4(vals[4], vals[5], vals[6], vals[7]);
                } else {
                    float mv = vals[0]; int mi = v0;
                    #pragma unroll
                    for (int v = 1; v < 8; v++)
                        if (vals[v] > mv) { mv = vals[v]; mi = v0 + v; }
                    #pragma unroll
                    for (int o = 16; o > 0; o >>= 1) {
                        float ovv = __shfl_down_sync(0xffffffffu, mv, o);
                        int   oii = __shfl_down_sync(0xffffffffu, mi, o);
                        if (ovv > mv || (ovv == mv && oii < mi)) { mv = ovv; mi = oii; }
                    }
                    if (vg == 0) atomicMax(&g_amax[b], amax_pack(mv, mi));
                }
            }
        }
        gsync();

        // ---- pick token, gather next embedding into g_x
        if (t < Tt - 1 && cta < Bb) {
            if (tid == 0) {
                ull pv = __ldcg((const ull*)&g_amax[cta]);
                s_tok = (int)(0xFFFFFFFFu - (unsigned)(pv & 0xFFFFFFFFull));
                atomicExch(&g_amax[cta], 0ull);   // reset for next step
            }
            __syncthreads();
            int tok = s_tok;
            float2 e2 = *(const float2*)(emb + (size_t)tok * Ee + tid * 2);
            __stcg(&g_x[(tid * 2) * Bb + cta],     e2.x);
            __stcg(&g_x[(tid * 2 + 1) * Bb + cta], e2.y);
        }
        gsync();
    }
}

// ---------------- host driver ----------------------------------------------
extern "C" void kernel_launch(void* const* d_in, const int* in_sizes, int n_in,
                              void* d_out, int out_size) {
    const int*   x    = (const int*)d_in[0];
    const float* emb  = (const float*)d_in[1];
    const float* W_ih = (const float*)d_in[2];   // [2][2048][512]
    const float* W_hh = (const float*)d_in[3];   // [2][2048][512]
    const float* b_ih = (const float*)d_in[4];   // [2][2048]
    const float* b_hh = (const float*)d_in[5];
    const float* W_fc = (const float*)d_in[6];   // [32000][512]
    const float* b_fc = (const float*)d_in[7];
    float* out = (float*)d_out;

    const int SMEM = 32768 * (int)sizeof(float);   // 128 KB gate weights
    cudaFuncSetAttribute(kmain, cudaFuncAttributeMaxDynamicSharedMemorySize, SMEM);

    // ONE launch: prep + all 256 timesteps (graph = 1 node)
    kmain<<<GRID, 256, SMEM>>>(x, emb, W_ih, W_hh, b_ih, b_hh, W_fc, b_fc, out);
}